// round 15
// baseline (speedup 1.0000x reference)
#include <cuda_runtime.h>
#include <cuda_fp16.h>
#include <math.h>
#include <stdint.h>

#define NN 8192
#define DD 128
#define NCENT 64
#define NCLS 7
#define NLAYER 4

#define MINN 1e-15f
#define EPSF 1e-5f
#define MAXNRM (1.0f - 1e-5f)

#define BM 64
#define STAGE_WORDS 6144
#define SMEMSZ (3 * STAGE_WORDS * 4)

#define ADJ_SCALE 8192.0f
#define ADJ_CSCALE 0.0001220703125f  // 2^-13

// ---------------- scratch ----------------
static __device__ uint32_t g_adjh[(size_t)NN * (NN / 32) * 16];
static __device__ uint32_t g_hh[NN * 4 * 16];
static __device__ float g_h[NN * DD];
static __device__ float g_res[NN * DD];
static __device__ uint32_t g_logTsw[DD * (NN / 32) * 16];
static __device__ float g_part[2][NN * DD];
static __device__ float g_hypb[NLAYER * DD];
static __device__ uint32_t g_Wsw[NLAYER * DD * 4 * 16];
static __device__ float g_dsum[NCENT];
static __device__ float g_z[NN * NCLS];

// ---------------- helpers ----------------
__device__ __forceinline__ float wsum(float v) {
    v += __shfl_xor_sync(0xffffffffu, v, 16);
    v += __shfl_xor_sync(0xffffffffu, v, 8);
    v += __shfl_xor_sync(0xffffffffu, v, 4);
    v += __shfl_xor_sync(0xffffffffu, v, 2);
    v += __shfl_xor_sync(0xffffffffu, v, 1);
    return v;
}
__device__ __forceinline__ float artanhf_(float x) {
    x = fminf(fmaxf(x, -1.0f + EPSF), 1.0f - EPSF);
    return 0.5f * (log1pf(x) - log1pf(-x));
}
__device__ __forceinline__ float rnorm4(const float v[4]) {
    float s = v[0] * v[0] + v[1] * v[1] + v[2] * v[2] + v[3] * v[3];
    s = wsum(s);
    return fmaxf(sqrtf(s), MINN);
}
__device__ __forceinline__ void proj4(float v[4]) {
    float n = rnorm4(v);
    if (n > MAXNRM) {
        float s = MAXNRM / n;
        v[0] *= s; v[1] *= s; v[2] *= s; v[3] *= s;
    }
}
__device__ __forceinline__ void expmap04(float v[4]) {
    float n = rnorm4(v);
    float s = tanhf(n) / n;
    v[0] *= s; v[1] *= s; v[2] *= s; v[3] *= s;
}
__device__ __forceinline__ void logmap04(float v[4]) {
    float n = rnorm4(v);
    float s = artanhf_(n) / n;
    v[0] *= s; v[1] *= s; v[2] *= s; v[3] *= s;
}
__device__ __forceinline__ uint32_t h2pack(float a, float b) {
    __half2 h = __floats2half2_rn(a, b);
    return *(uint32_t*)&h;
}
__device__ __forceinline__ void mmah16(float c[4], uint32_t a0, uint32_t a1,
                                       uint32_t a2, uint32_t a3,
                                       uint32_t b0, uint32_t b1) {
    asm volatile(
        "mma.sync.aligned.m16n8k16.row.col.f32.f16.f16.f32 "
        "{%0,%1,%2,%3},{%4,%5,%6,%7},{%8,%9},{%0,%1,%2,%3};"
        : "+f"(c[0]), "+f"(c[1]), "+f"(c[2]), "+f"(c[3])
        : "r"(a0), "r"(a1), "r"(a2), "r"(a3), "r"(b0), "r"(b1));
}
__device__ __forceinline__ uint32_t smem_u32(const void* p) {
    uint32_t a;
    asm("{ .reg .u64 t; cvta.to.shared.u64 t, %1; cvt.u32.u64 %0, t; }" : "=r"(a) : "l"(p));
    return a;
}
__device__ __forceinline__ void cpa16(uint32_t dst, const void* src) {
    asm volatile("cp.async.cg.shared.global [%0], [%1], 16;" :: "r"(dst), "l"(src));
}
#define CPA_COMMIT() asm volatile("cp.async.commit_group;" ::: "memory")
#define CPA_WAIT1() asm volatile("cp.async.wait_group 1;" ::: "memory")
#define CPA_WAIT0() asm volatile("cp.async.wait_group 0;" ::: "memory")

// ---------------- fp16 GEMM: BM=64, BN=128, BK=64, 8 warps --------
__global__ void __launch_bounds__(256, 2)
k_hgemm(const uint32_t* __restrict__ Asw, const uint32_t* __restrict__ Bsw,
        int kbA, int kbB, int iters, int part0, float cscale,
        float* __restrict__ Cbase) {
    extern __shared__ uint32_t smh[];
    const uint32_t smb = smem_u32(smh);
    const int tid = threadIdx.x;
    const int m0 = blockIdx.x * BM;
    const int kpart = part0 + blockIdx.y;
    const int kb0 = kpart * 2 * iters;
    float* Cout = Cbase + (size_t)kpart * NN * DD;

    int arr[2], ajj[2];
    uint32_t adst[2];
#pragma unroll
    for (int p = 0; p < 2; p++) {
        int idx = p * 256 + tid;
        int r = idx >> 3, j = idx & 7;
        arr[p] = r; ajj[p] = j;
        adst[p] = (uint32_t)((r * 32 + (((j >> 2) ^ (r & 1)) << 4) + (j & 3) * 4) * 4);
    }
    int brr[4], bjj[4];
    uint32_t bdst[4];
#pragma unroll
    for (int p = 0; p < 4; p++) {
        int idx = p * 256 + tid;
        int r = idx >> 3, j = idx & 7;
        brr[p] = r; bjj[p] = j;
        bdst[p] = (uint32_t)(8192 + (r * 32 + (((j >> 2) ^ (r & 1)) << 4) + (j & 3) * 4) * 4);
    }
    const uint32_t* aBase = Asw + (size_t)m0 * kbA * 16 + (size_t)kb0 * 16;
    const uint32_t* bBase = Bsw + (size_t)kb0 * 16;

#define ISSUE(stage, it)                                                      \
    do {                                                                      \
        uint32_t _s = smb + (uint32_t)(stage) * (STAGE_WORDS * 4);            \
        _Pragma("unroll") for (int p = 0; p < 2; p++)                         \
            cpa16(_s + adst[p],                                               \
                  aBase + (size_t)arr[p] * kbA * 16 + (it) * 32 + ajj[p] * 4);\
        _Pragma("unroll") for (int p = 0; p < 4; p++)                         \
            cpa16(_s + bdst[p],                                               \
                  bBase + (size_t)brr[p] * kbB * 16 + (it) * 32 + bjj[p] * 4);\
    } while (0)

    const int w = tid >> 5, lane = tid & 31;
    const int rr = lane >> 2, c = lane & 3;
    const int m0w = (w & 1) * 32, n0w = (w >> 1) * 32;
    const int pcw = 4 * (c ^ ((rr >> 1) & 3));
    const int rh = (rr & 1) << 4;
    int hoff[2];
    hoff[0] = (0 ^ rh) + pcw;
    hoff[1] = (16 ^ rh) + pcw;

    float acc[2][4][4];
#pragma unroll
    for (int mt = 0; mt < 2; mt++)
#pragma unroll
        for (int nt = 0; nt < 4; nt++)
#pragma unroll
            for (int e = 0; e < 4; e++) acc[mt][nt][e] = 0.0f;

    ISSUE(0, 0); CPA_COMMIT();
    if (iters > 1) ISSUE(1, 1);
    CPA_COMMIT();

    for (int i = 0; i < iters; i++) {
        if (i + 2 < iters) { CPA_WAIT1(); } else { CPA_WAIT0(); }
        __syncthreads();
        if (i + 2 < iters) ISSUE((i + 2) % 3, i + 2);
        CPA_COMMIT();

        const uint32_t* sA = smh + (size_t)(i % 3) * STAGE_WORDS;
        const uint32_t* sB = sA + 2048;
#pragma unroll
        for (int hb = 0; hb < 2; hb++) {
            uint4 a0[2], a1[2];
#pragma unroll
            for (int mt = 0; mt < 2; mt++) {
                int base = (m0w + mt * 16 + rr) * 32 + hoff[hb];
                a0[mt] = *(const uint4*)(sA + base);
                a1[mt] = *(const uint4*)(sA + base + 256);
            }
#pragma unroll
            for (int nt = 0; nt < 4; nt++) {
                uint4 b = *(const uint4*)(sB + (n0w + nt * 8 + rr) * 32 + hoff[hb]);
#pragma unroll
                for (int mt = 0; mt < 2; mt++)
                    mmah16(acc[mt][nt], a0[mt].x, a1[mt].x, a0[mt].y, a1[mt].y, b.x, b.y);
#pragma unroll
                for (int mt = 0; mt < 2; mt++)
                    mmah16(acc[mt][nt], a0[mt].z, a1[mt].z, a0[mt].w, a1[mt].w, b.z, b.w);
            }
        }
    }
#undef ISSUE

#pragma unroll
    for (int mt = 0; mt < 2; mt++) {
        int row = m0 + m0w + mt * 16 + rr;
#pragma unroll
        for (int nt = 0; nt < 4; nt++) {
            int col = n0w + nt * 8 + 2 * c;
            *(float2*)&Cout[(size_t)row * DD + col] =
                make_float2(acc[mt][nt][0] * cscale, acc[mt][nt][1] * cscale);
            *(float2*)&Cout[(size_t)(row + 8) * DD + col] =
                make_float2(acc[mt][nt][2] * cscale, acc[mt][nt][3] * cscale);
        }
    }
}

// ---------------- prep kernels ----------------
__global__ void k_prep_adj(const float* __restrict__ adj, int kboff) {
    int unit = blockIdx.x * 256 + threadIdx.x;
    int row = unit >> 7, kb = (unit & 127) + kboff;
    const float* src = adj + (size_t)row * NN + kb * 32;
    uint32_t* dst = g_adjh + ((size_t)row * 256 + kb) * 16;
    float fl[32];
#pragma unroll
    for (int q = 0; q < 8; q++) *(float4*)(fl + q * 4) = *(const float4*)(src + q * 4);
    int s4r = (row >> 1) & 3;
#pragma unroll
    for (int c = 0; c < 4; c++) {
        uint4 o;
        o.x = h2pack(fl[2 * c] * ADJ_SCALE, fl[2 * c + 1] * ADJ_SCALE);
        o.y = h2pack(fl[2 * (c + 4)] * ADJ_SCALE, fl[2 * (c + 4) + 1] * ADJ_SCALE);
        o.z = h2pack(fl[2 * (c + 8)] * ADJ_SCALE, fl[2 * (c + 8) + 1] * ADJ_SCALE);
        o.w = h2pack(fl[2 * (c + 12)] * ADJ_SCALE, fl[2 * (c + 12) + 1] * ADJ_SCALE);
        *(uint4*)(dst + 4 * (c ^ s4r)) = o;
    }
}

// merged: W conversion (blocks 0..31) + hyp bias (block 32)
__global__ void k_prepWb(const float* __restrict__ W, const float* __restrict__ b) {
    if (blockIdx.x < 32) {
        int idx = blockIdx.x * 256 + threadIdx.x;  // 8192
        int unit = idx >> 2, sub = idx & 3;
        int l = unit >> 9;
        int r = (unit >> 2) & 127;
        int kb = unit & 3;
        const float* src = W + ((size_t)(l * 128 + r)) * 128 + kb * 32;
        uint32_t* dst = g_Wsw + ((size_t)((l * 128 + r) * 4 + kb)) * 16;
        int s4r = (r >> 1) & 3;
#pragma unroll
        for (int j = 0; j < 4; j++) {
            int ww = sub * 4 + j;
            int P = 4 * ((ww & 3) ^ s4r) + (ww >> 2);
            dst[P] = h2pack(src[2 * ww], src[2 * ww + 1]);
        }
    } else if (threadIdx.x < 128) {
        int l = threadIdx.x >> 5;
        int lane = threadIdx.x & 31;
        float v[4];
#pragma unroll
        for (int i = 0; i < 4; i++) v[i] = b[l * DD + lane + i * 32];
        expmap04(v);
        proj4(v);
#pragma unroll
        for (int i = 0; i < 4; i++) g_hypb[l * DD + lane + i * 32] = v[i];
    }
}

__device__ __forceinline__ void emit_hh(int row, int lane, const float v[4]) {
    float vn[4];
#pragma unroll
    for (int i = 0; i < 4; i++) vn[i] = __shfl_down_sync(0xffffffffu, v[i], 1);
    if (!(lane & 1)) {
        int s4r = (row >> 1) & 3;
        int ww = lane >> 1;
        int P = 4 * ((ww & 3) ^ s4r) + (ww >> 2);
        uint32_t* dst = g_hh + (size_t)row * 64 + P;
#pragma unroll
        for (int i = 0; i < 4; i++) dst[i * 16] = h2pack(v[i], vn[i]);
    }
}

// ---------------- pointwise ----------------
__global__ void k_in(const float* __restrict__ x) {
    if (blockIdx.x == 0 && threadIdx.x < NCENT) g_dsum[threadIdx.x] = 0.0f;
    int w = (blockIdx.x * blockDim.x + threadIdx.x) >> 5;
    int lane = threadIdx.x & 31;
    if (w >= NN) return;
    const float* r = x + w * DD + lane;
    float v[4];
#pragma unroll
    for (int i = 0; i < 4; i++) v[i] = r[i * 32];
    expmap04(v);
    proj4(v);
    int o = w * DD + lane;
#pragma unroll
    for (int i = 0; i < 4; i++) {
        g_h[o + i * 32] = v[i];
        g_res[o + i * 32] = v[i];
    }
    emit_hh(w, lane, v);
}

__global__ void __launch_bounds__(512)
k_post_linear_t(int l) {
    __shared__ float sT[32][129];
    int w = threadIdx.x >> 5, lane = threadIdx.x & 31;
    int blk = blockIdx.x;
    int n0 = blk * 32;
    float y[4];
#pragma unroll
    for (int i = 0; i < 4; i++) y[i] = g_hypb[l * DD + lane + i * 32];
    float y2b = wsum(y[0] * y[0] + y[1] * y[1] + y[2] * y[2] + y[3] * y[3]);

#pragma unroll
    for (int s = 0; s < 2; s++) {
        int node = n0 + w * 2 + s;
        int o = node * DD + lane;
        float mv[4], hx[4];
#pragma unroll
        for (int i = 0; i < 4; i++) {
            mv[i] = g_part[0][o + i * 32] + g_part[1][o + i * 32];
            hx[i] = g_h[o + i * 32];
        }
        float xn = rnorm4(hx);
        float mxn = rnorm4(mv);
        float sc = tanhf(mxn / xn * artanhf_(xn)) / mxn;
#pragma unroll
        for (int i = 0; i < 4; i++) mv[i] *= sc;
        proj4(mv);
        float x2 = wsum(mv[0] * mv[0] + mv[1] * mv[1] + mv[2] * mv[2] + mv[3] * mv[3]);
        float xy = wsum(mv[0] * y[0] + mv[1] * y[1] + mv[2] * y[2] + mv[3] * y[3]);
        float ca = 1.0f + 2.0f * xy + y2b;
        float cbf = 1.0f - x2;
        float den = fmaxf(1.0f + 2.0f * xy + x2 * y2b, MINN);
#pragma unroll
        for (int i = 0; i < 4; i++) mv[i] = (ca * mv[i] + cbf * y[i]) / den;
        proj4(mv);
        logmap04(mv);
#pragma unroll
        for (int i = 0; i < 4; i++) sT[w * 2 + s][lane + i * 32] = mv[i];
    }
    __syncthreads();
    int d = threadIdx.x >> 2;
    int q = threadIdx.x & 3;
    int s4r = (d >> 1) & 3;
    uint32_t* dst = g_logTsw + ((size_t)d * (NN / 32) + blk) * 16;
#pragma unroll
    for (int j = 0; j < 4; j++) {
        int ww = q * 4 + j;
        int P = 4 * ((ww & 3) ^ s4r) + (ww >> 2);
        dst[P] = h2pack(sT[2 * ww][d], sT[2 * ww + 1][d]);
    }
}

__global__ void k_post_agg(int add_res, int save_res) {
    int w = (blockIdx.x * blockDim.x + threadIdx.x) >> 5;
    int lane = threadIdx.x & 31;
    if (w >= NN) return;
    int o = w * DD + lane;
    float v[4];
#pragma unroll
    for (int i = 0; i < 4; i++) {
        int oo = o + i * 32;
        v[i] = g_part[0][oo] + g_part[1][oo];
    }
    expmap04(v); proj4(v);
    logmap04(v);
#pragma unroll
    for (int i = 0; i < 4; i++) v[i] = fmaxf(v[i], 0.0f);
    expmap04(v); proj4(v);
    if (add_res) {
#pragma unroll
        for (int i = 0; i < 4; i++) v[i] += g_res[o + i * 32];
    }
#pragma unroll
    for (int i = 0; i < 4; i++) g_h[o + i * 32] = v[i];
    if (save_res) {
#pragma unroll
        for (int i = 0; i < 4; i++) g_res[o + i * 32] = v[i];
    }
    emit_hh(w, lane, v);
}

__global__ void k_cent(const float* __restrict__ cent) {
    __shared__ float sC[NCENT * 129];
    __shared__ float hs[4][DD];
    __shared__ float red[4][NCENT];
    int tx = threadIdx.x, ty = threadIdx.y;
    int tid = ty * 64 + tx;
    for (int idx = tid; idx < NCENT * DD; idx += 256)
        sC[(idx >> 7) * 129 + (idx & 127)] = cent[idx];
    int n = (blockIdx.x << 2) + ty;
    const float* hr = g_h + (size_t)n * DD;
    hs[ty][tx] = hr[tx];
    hs[ty][tx + 64] = hr[tx + 64];
    __syncthreads();
    const float* cr = sC + tx * 129;
    float x2 = 0.f, xy = 0.f, y2 = 0.f;
#pragma unroll 4
    for (int k = 0; k < DD; k++) {
        float a = hs[ty][k];
        float b = cr[k];
        x2 += a * a; xy += a * b; y2 += b * b;
    }
    float A = 1.0f - 2.0f * xy + y2;
    float Bc = 1.0f - x2;
    float nn = 0.f;
#pragma unroll 4
    for (int k = 0; k < DD; k++) {
        float t = Bc * cr[k] - A * hs[ty][k];
        nn += t * t;
    }
    float den = fmaxf(1.0f - 2.0f * xy + x2 * y2, MINN);
    float d = fmaxf(sqrtf(nn) / den, MINN);
    red[ty][tx] = 2.0f * artanhf_(d);
    __syncthreads();
    if (ty == 0)
        atomicAdd(&g_dsum[tx], red[0][tx] + red[1][tx] + red[2][tx] + red[3][tx]);
}

__global__ void k_z(const float* __restrict__ W1, const float* __restrict__ b1) {
    int w = (blockIdx.x * blockDim.x + threadIdx.x) >> 5;
    int lane = threadIdx.x & 31;
    if (w >= NN) return;
    int o = w * DD + lane;
    float v[4];
#pragma unroll
    for (int i = 0; i < 4; i++) v[i] = g_h[o + i * 32];
    logmap04(v);
#pragma unroll
    for (int cls = 0; cls < NCLS; cls++) {
        float p = 0.f;
#pragma unroll
        for (int i = 0; i < 4; i++) p += v[i] * W1[cls * DD + lane + i * 32];
        p = wsum(p);
        if (lane == 0) g_z[w * NCLS + cls] = p + b1[cls];
    }
}

__global__ void k_sm_final(float* __restrict__ out, int hr_off) {
    if (blockIdx.x < NCLS) {
        int cls = blockIdx.x;
        int t = threadIdx.x;
        __shared__ float sh[256];
        float m = -1e30f;
        for (int n = t; n < NN; n += 256) m = fmaxf(m, g_z[n * NCLS + cls]);
        sh[t] = m; __syncthreads();
        for (int s = 128; s; s >>= 1) { if (t < s) sh[t] = fmaxf(sh[t], sh[t + s]); __syncthreads(); }
        m = sh[0]; __syncthreads();
        float ss = 0.f;
        for (int n = t; n < NN; n += 256) ss += expf(g_z[n * NCLS + cls] - m);
        sh[t] = ss; __syncthreads();
        for (int s = 128; s; s >>= 1) { if (t < s) sh[t] += sh[t + s]; __syncthreads(); }
        float inv = 1.0f / sh[0];
        for (int n = t; n < NN; n += 256)
            out[7 + n * NCLS + cls] = expf(g_z[n * NCLS + cls] - m) * inv;
    } else {
        int t = threadIdx.x;
        __shared__ float sh[64];
        if (t < 64) {
            float r = g_dsum[t] * (1.0f / (float)NN);
            sh[t] = r * r;
        }
        __syncthreads();
        if (t == 0) {
            float s = 0.f;
            for (int i = 0; i < 64; i++) s += sh[i];
            sh[0] = s;
        }
        __syncthreads();
        if (t < 64) {
            float nrm = fmaxf(sqrtf(sh[0]), MINN);
            float s2 = artanhf_(nrm) / nrm;
            out[hr_off + t] = g_dsum[t] * (1.0f / (float)NN) * s2;
            if (t < NCLS) out[t] = 1.0f;
        }
    }
}

// ---------------- launch ----------------
extern "C" void kernel_launch(void* const* d_in, const int* in_sizes, int n_in,
                              void* d_out, int out_size) {
    const float* x = (const float*)d_in[0];
    const float* adj = (const float*)d_in[1];
    const float* W_conv = (const float*)d_in[3];
    const float* b_conv = (const float*)d_in[4];
    const float* cent = (const float*)d_in[5];
    const float* W1 = (const float*)d_in[8];
    const float* b1 = (const float*)d_in[9];
    float* out = (float*)d_out;

    float* p_part = 0;
    uint32_t *p_adjh = 0, *p_hh = 0, *p_logTsw = 0, *p_Wsw = 0;
    cudaGetSymbolAddress((void**)&p_part, g_part);
    cudaGetSymbolAddress((void**)&p_adjh, g_adjh);
    cudaGetSymbolAddress((void**)&p_hh, g_hh);
    cudaGetSymbolAddress((void**)&p_logTsw, g_logTsw);
    cudaGetSymbolAddress((void**)&p_Wsw, g_Wsw);

    cudaFuncSetAttribute(k_hgemm, cudaFuncAttributeMaxDynamicSharedMemorySize, SMEMSZ);

    cudaStream_t s1;
    cudaStreamCreateWithFlags(&s1, cudaStreamNonBlocking);
    cudaEvent_t eFork, ePW, eP0, eP1, eFork2, eJoin2;
    cudaEventCreateWithFlags(&eFork, cudaEventDisableTiming);
    cudaEventCreateWithFlags(&ePW, cudaEventDisableTiming);
    cudaEventCreateWithFlags(&eP0, cudaEventDisableTiming);
    cudaEventCreateWithFlags(&eP1, cudaEventDisableTiming);
    cudaEventCreateWithFlags(&eFork2, cudaEventDisableTiming);
    cudaEventCreateWithFlags(&eJoin2, cudaEventDisableTiming);

    // side stream: W/bias prep, then two adj prep chunks
    cudaEventRecord(eFork, 0);
    cudaStreamWaitEvent(s1, eFork, 0);
    k_prepWb<<<33, 256, 0, s1>>>(W_conv, b_conv);
    cudaEventRecord(ePW, s1);
    k_prep_adj<<<4096, 256, 0, s1>>>(adj, 0);
    cudaEventRecord(eP0, s1);
    k_prep_adj<<<4096, 256, 0, s1>>>(adj, 128);
    cudaEventRecord(eP1, s1);

    // main stream head
    k_in<<<NN / 8, 256>>>(x);
    cudaStreamWaitEvent(0, ePW, 0);
    k_hgemm<<<dim3(NN / BM, 2), 256, SMEMSZ>>>(
        p_hh, p_Wsw, 4, 4, 1, 0, 1.0f, p_part);
    k_post_linear_t<<<NN / 32, 512>>>(0);

    // layer-0 agg (split-K 2), halves gated on prep chunks
    cudaStreamWaitEvent(0, eP0, 0);
    k_hgemm<<<dim3(NN / BM, 1), 256, SMEMSZ>>>(
        p_adjh, p_logTsw, 256, 256, 64, 0, ADJ_CSCALE, p_part);
    cudaStreamWaitEvent(0, eP1, 0);
    k_hgemm<<<dim3(NN / BM, 1), 256, SMEMSZ>>>(
        p_adjh, p_logTsw, 256, 256, 64, 1, ADJ_CSCALE, p_part);
    k_post_agg<<<NN / 8, 256>>>(0, 0);

    for (int l = 1; l < NLAYER; l++) {
        k_hgemm<<<dim3(NN / BM, 2), 256, SMEMSZ>>>(
            p_hh, p_Wsw + (size_t)l * DD * 4 * 16, 4, 4, 1, 0, 1.0f, p_part);
        k_post_linear_t<<<NN / 32, 512>>>(l);
        k_hgemm<<<dim3(NN / BM, 2), 256, SMEMSZ>>>(
            p_adjh, p_logTsw, 256, 256, 64, 0, ADJ_CSCALE, p_part);
        int ar = (l == 1 || l == 3) ? 1 : 0;
        int sr = (l == 1) ? 1 : 0;
        k_post_agg<<<NN / 8, 256>>>(ar, sr);
    }

    // tail: k_z concurrent with k_cent
    cudaEventRecord(eFork2, 0);
    cudaStreamWaitEvent(s1, eFork2, 0);
    k_z<<<NN / 8, 256, 0, s1>>>(W1, b1);
    cudaEventRecord(eJoin2, s1);

    k_cent<<<NN / 4, dim3(64, 4)>>>(cent);
    cudaStreamWaitEvent(0, eJoin2, 0);
    k_sm_final<<<NCLS + 1, 256>>>(out, out_size - NCENT);
}

// round 16
// speedup vs baseline: 1.0087x; 1.0087x over previous
#include <cuda_runtime.h>
#include <cuda_fp16.h>
#include <math.h>
#include <stdint.h>

#define NN 8192
#define DD 128
#define NCENT 64
#define NCLS 7
#define NLAYER 4

#define MINN 1e-15f
#define EPSF 1e-5f
#define MAXNRM (1.0f - 1e-5f)

#define BM 64
#define STAGE_WORDS 6144
#define SMEMSZ (3 * STAGE_WORDS * 4)

#define ADJ_SCALE 8192.0f
#define ADJ_CSCALE 0.0001220703125f  // 2^-13

// ---------------- scratch ----------------
static __device__ uint32_t g_adjh[(size_t)NN * (NN / 32) * 16];
static __device__ uint32_t g_hh[NN * 4 * 16];
static __device__ float g_h[NN * DD];
static __device__ float g_res[NN * DD];
static __device__ uint32_t g_logTsw[DD * (NN / 32) * 16];
static __device__ float g_part[4][NN * DD];
static __device__ float g_hypb[NLAYER * DD];
static __device__ uint32_t g_Wsw[NLAYER * DD * 4 * 16];
static __device__ float g_dsum[NCENT];
static __device__ float g_z[NN * NCLS];

// ---------------- helpers ----------------
__device__ __forceinline__ float wsum(float v) {
    v += __shfl_xor_sync(0xffffffffu, v, 16);
    v += __shfl_xor_sync(0xffffffffu, v, 8);
    v += __shfl_xor_sync(0xffffffffu, v, 4);
    v += __shfl_xor_sync(0xffffffffu, v, 2);
    v += __shfl_xor_sync(0xffffffffu, v, 1);
    return v;
}
__device__ __forceinline__ float artanhf_(float x) {
    x = fminf(fmaxf(x, -1.0f + EPSF), 1.0f - EPSF);
    return 0.5f * (log1pf(x) - log1pf(-x));
}
__device__ __forceinline__ float rnorm4(const float v[4]) {
    float s = v[0] * v[0] + v[1] * v[1] + v[2] * v[2] + v[3] * v[3];
    s = wsum(s);
    return fmaxf(sqrtf(s), MINN);
}
__device__ __forceinline__ void proj4(float v[4]) {
    float n = rnorm4(v);
    if (n > MAXNRM) {
        float s = MAXNRM / n;
        v[0] *= s; v[1] *= s; v[2] *= s; v[3] *= s;
    }
}
__device__ __forceinline__ void expmap04(float v[4]) {
    float n = rnorm4(v);
    float s = tanhf(n) / n;
    v[0] *= s; v[1] *= s; v[2] *= s; v[3] *= s;
}
__device__ __forceinline__ void logmap04(float v[4]) {
    float n = rnorm4(v);
    float s = artanhf_(n) / n;
    v[0] *= s; v[1] *= s; v[2] *= s; v[3] *= s;
}
__device__ __forceinline__ uint32_t h2pack(float a, float b) {
    __half2 h = __floats2half2_rn(a, b);
    return *(uint32_t*)&h;
}
__device__ __forceinline__ void mmah16(float c[4], uint32_t a0, uint32_t a1,
                                       uint32_t a2, uint32_t a3,
                                       uint32_t b0, uint32_t b1) {
    asm volatile(
        "mma.sync.aligned.m16n8k16.row.col.f32.f16.f16.f32 "
        "{%0,%1,%2,%3},{%4,%5,%6,%7},{%8,%9},{%0,%1,%2,%3};"
        : "+f"(c[0]), "+f"(c[1]), "+f"(c[2]), "+f"(c[3])
        : "r"(a0), "r"(a1), "r"(a2), "r"(a3), "r"(b0), "r"(b1));
}
__device__ __forceinline__ uint32_t smem_u32(const void* p) {
    uint32_t a;
    asm("{ .reg .u64 t; cvta.to.shared.u64 t, %1; cvt.u32.u64 %0, t; }" : "=r"(a) : "l"(p));
    return a;
}
__device__ __forceinline__ void cpa16(uint32_t dst, const void* src) {
    asm volatile("cp.async.cg.shared.global [%0], [%1], 16;" :: "r"(dst), "l"(src));
}
#define CPA_COMMIT() asm volatile("cp.async.commit_group;" ::: "memory")
#define CPA_WAIT1() asm volatile("cp.async.wait_group 1;" ::: "memory")
#define CPA_WAIT0() asm volatile("cp.async.wait_group 0;" ::: "memory")

// ---------------- fp16 GEMM: BM=64, BN=128, BK=64, 8 warps --------
__global__ void __launch_bounds__(256, 2)
k_hgemm(const uint32_t* __restrict__ Asw, const uint32_t* __restrict__ Bsw,
        int kbA, int kbB, int iters, int part0, float cscale,
        float* __restrict__ Cbase) {
    extern __shared__ uint32_t smh[];
    const uint32_t smb = smem_u32(smh);
    const int tid = threadIdx.x;
    const int m0 = blockIdx.x * BM;
    const int kpart = part0 + blockIdx.y;
    const int kb0 = kpart * 2 * iters;
    float* Cout = Cbase + (size_t)kpart * NN * DD;

    int arr[2], ajj[2];
    uint32_t adst[2];
#pragma unroll
    for (int p = 0; p < 2; p++) {
        int idx = p * 256 + tid;
        int r = idx >> 3, j = idx & 7;
        arr[p] = r; ajj[p] = j;
        adst[p] = (uint32_t)((r * 32 + (((j >> 2) ^ (r & 1)) << 4) + (j & 3) * 4) * 4);
    }
    int brr[4], bjj[4];
    uint32_t bdst[4];
#pragma unroll
    for (int p = 0; p < 4; p++) {
        int idx = p * 256 + tid;
        int r = idx >> 3, j = idx & 7;
        brr[p] = r; bjj[p] = j;
        bdst[p] = (uint32_t)(8192 + (r * 32 + (((j >> 2) ^ (r & 1)) << 4) + (j & 3) * 4) * 4);
    }
    const uint32_t* aBase = Asw + (size_t)m0 * kbA * 16 + (size_t)kb0 * 16;
    const uint32_t* bBase = Bsw + (size_t)kb0 * 16;

#define ISSUE(stage, it)                                                      \
    do {                                                                      \
        uint32_t _s = smb + (uint32_t)(stage) * (STAGE_WORDS * 4);            \
        _Pragma("unroll") for (int p = 0; p < 2; p++)                         \
            cpa16(_s + adst[p],                                               \
                  aBase + (size_t)arr[p] * kbA * 16 + (it) * 32 + ajj[p] * 4);\
        _Pragma("unroll") for (int p = 0; p < 4; p++)                         \
            cpa16(_s + bdst[p],                                               \
                  bBase + (size_t)brr[p] * kbB * 16 + (it) * 32 + bjj[p] * 4);\
    } while (0)

    const int w = tid >> 5, lane = tid & 31;
    const int rr = lane >> 2, c = lane & 3;
    const int m0w = (w & 1) * 32, n0w = (w >> 1) * 32;
    const int pcw = 4 * (c ^ ((rr >> 1) & 3));
    const int rh = (rr & 1) << 4;
    int hoff[2];
    hoff[0] = (0 ^ rh) + pcw;
    hoff[1] = (16 ^ rh) + pcw;

    float acc[2][4][4];
#pragma unroll
    for (int mt = 0; mt < 2; mt++)
#pragma unroll
        for (int nt = 0; nt < 4; nt++)
#pragma unroll
            for (int e = 0; e < 4; e++) acc[mt][nt][e] = 0.0f;

    ISSUE(0, 0); CPA_COMMIT();
    if (iters > 1) ISSUE(1, 1);
    CPA_COMMIT();

    for (int i = 0; i < iters; i++) {
        if (i + 2 < iters) { CPA_WAIT1(); } else { CPA_WAIT0(); }
        __syncthreads();
        if (i + 2 < iters) ISSUE((i + 2) % 3, i + 2);
        CPA_COMMIT();

        const uint32_t* sA = smh + (size_t)(i % 3) * STAGE_WORDS;
        const uint32_t* sB = sA + 2048;
#pragma unroll
        for (int hb = 0; hb < 2; hb++) {
            uint4 a0[2], a1[2];
#pragma unroll
            for (int mt = 0; mt < 2; mt++) {
                int base = (m0w + mt * 16 + rr) * 32 + hoff[hb];
                a0[mt] = *(const uint4*)(sA + base);
                a1[mt] = *(const uint4*)(sA + base + 256);
            }
#pragma unroll
            for (int nt = 0; nt < 4; nt++) {
                uint4 b = *(const uint4*)(sB + (n0w + nt * 8 + rr) * 32 + hoff[hb]);
#pragma unroll
                for (int mt = 0; mt < 2; mt++)
                    mmah16(acc[mt][nt], a0[mt].x, a1[mt].x, a0[mt].y, a1[mt].y, b.x, b.y);
#pragma unroll
                for (int mt = 0; mt < 2; mt++)
                    mmah16(acc[mt][nt], a0[mt].z, a1[mt].z, a0[mt].w, a1[mt].w, b.z, b.w);
            }
        }
    }
#undef ISSUE

#pragma unroll
    for (int mt = 0; mt < 2; mt++) {
        int row = m0 + m0w + mt * 16 + rr;
#pragma unroll
        for (int nt = 0; nt < 4; nt++) {
            int col = n0w + nt * 8 + 2 * c;
            *(float2*)&Cout[(size_t)row * DD + col] =
                make_float2(acc[mt][nt][0] * cscale, acc[mt][nt][1] * cscale);
            *(float2*)&Cout[(size_t)(row + 8) * DD + col] =
                make_float2(acc[mt][nt][2] * cscale, acc[mt][nt][3] * cscale);
        }
    }
}

// ---------------- prep kernels ----------------
__global__ void k_prep_adj(const float* __restrict__ adj, int kboff) {
    int unit = blockIdx.x * 256 + threadIdx.x;
    int row = unit >> 7, kb = (unit & 127) + kboff;
    const float* src = adj + (size_t)row * NN + kb * 32;
    uint32_t* dst = g_adjh + ((size_t)row * 256 + kb) * 16;
    float fl[32];
#pragma unroll
    for (int q = 0; q < 8; q++) *(float4*)(fl + q * 4) = *(const float4*)(src + q * 4);
    int s4r = (row >> 1) & 3;
#pragma unroll
    for (int c = 0; c < 4; c++) {
        uint4 o;
        o.x = h2pack(fl[2 * c] * ADJ_SCALE, fl[2 * c + 1] * ADJ_SCALE);
        o.y = h2pack(fl[2 * (c + 4)] * ADJ_SCALE, fl[2 * (c + 4) + 1] * ADJ_SCALE);
        o.z = h2pack(fl[2 * (c + 8)] * ADJ_SCALE, fl[2 * (c + 8) + 1] * ADJ_SCALE);
        o.w = h2pack(fl[2 * (c + 12)] * ADJ_SCALE, fl[2 * (c + 12) + 1] * ADJ_SCALE);
        *(uint4*)(dst + 4 * (c ^ s4r)) = o;
    }
}

__global__ void k_prepWb(const float* __restrict__ W, const float* __restrict__ b) {
    if (blockIdx.x < 32) {
        int idx = blockIdx.x * 256 + threadIdx.x;
        int unit = idx >> 2, sub = idx & 3;
        int l = unit >> 9;
        int r = (unit >> 2) & 127;
        int kb = unit & 3;
        const float* src = W + ((size_t)(l * 128 + r)) * 128 + kb * 32;
        uint32_t* dst = g_Wsw + ((size_t)((l * 128 + r) * 4 + kb)) * 16;
        int s4r = (r >> 1) & 3;
#pragma unroll
        for (int j = 0; j < 4; j++) {
            int ww = sub * 4 + j;
            int P = 4 * ((ww & 3) ^ s4r) + (ww >> 2);
            dst[P] = h2pack(src[2 * ww], src[2 * ww + 1]);
        }
    } else if (threadIdx.x < 128) {
        int l = threadIdx.x >> 5;
        int lane = threadIdx.x & 31;
        float v[4];
#pragma unroll
        for (int i = 0; i < 4; i++) v[i] = b[l * DD + lane + i * 32];
        expmap04(v);
        proj4(v);
#pragma unroll
        for (int i = 0; i < 4; i++) g_hypb[l * DD + lane + i * 32] = v[i];
    }
}

__device__ __forceinline__ void emit_hh(int row, int lane, const float v[4]) {
    float vn[4];
#pragma unroll
    for (int i = 0; i < 4; i++) vn[i] = __shfl_down_sync(0xffffffffu, v[i], 1);
    if (!(lane & 1)) {
        int s4r = (row >> 1) & 3;
        int ww = lane >> 1;
        int P = 4 * ((ww & 3) ^ s4r) + (ww >> 2);
        uint32_t* dst = g_hh + (size_t)row * 64 + P;
#pragma unroll
        for (int i = 0; i < 4; i++) dst[i * 16] = h2pack(v[i], vn[i]);
    }
}

// ---------------- pointwise ----------------
__global__ void k_in(const float* __restrict__ x) {
    if (blockIdx.x == 0 && threadIdx.x < NCENT) g_dsum[threadIdx.x] = 0.0f;
    int w = (blockIdx.x * blockDim.x + threadIdx.x) >> 5;
    int lane = threadIdx.x & 31;
    if (w >= NN) return;
    const float* r = x + w * DD + lane;
    float v[4];
#pragma unroll
    for (int i = 0; i < 4; i++) v[i] = r[i * 32];
    expmap04(v);
    proj4(v);
    int o = w * DD + lane;
#pragma unroll
    for (int i = 0; i < 4; i++) {
        g_h[o + i * 32] = v[i];
        g_res[o + i * 32] = v[i];
    }
    emit_hh(w, lane, v);
}

__global__ void __launch_bounds__(512)
k_post_linear_t(int l) {
    __shared__ float sT[32][129];
    int w = threadIdx.x >> 5, lane = threadIdx.x & 31;
    int blk = blockIdx.x;
    int n0 = blk * 32;
    float y[4];
#pragma unroll
    for (int i = 0; i < 4; i++) y[i] = g_hypb[l * DD + lane + i * 32];
    float y2b = wsum(y[0] * y[0] + y[1] * y[1] + y[2] * y[2] + y[3] * y[3]);

#pragma unroll
    for (int s = 0; s < 2; s++) {
        int node = n0 + w * 2 + s;
        int o = node * DD + lane;
        float mv[4], hx[4];
#pragma unroll
        for (int i = 0; i < 4; i++) {
            mv[i] = g_part[0][o + i * 32] + g_part[1][o + i * 32];
            hx[i] = g_h[o + i * 32];
        }
        float xn = rnorm4(hx);
        float mxn = rnorm4(mv);
        float sc = tanhf(mxn / xn * artanhf_(xn)) / mxn;
#pragma unroll
        for (int i = 0; i < 4; i++) mv[i] *= sc;
        proj4(mv);
        float x2 = wsum(mv[0] * mv[0] + mv[1] * mv[1] + mv[2] * mv[2] + mv[3] * mv[3]);
        float xy = wsum(mv[0] * y[0] + mv[1] * y[1] + mv[2] * y[2] + mv[3] * y[3]);
        float ca = 1.0f + 2.0f * xy + y2b;
        float cbf = 1.0f - x2;
        float den = fmaxf(1.0f + 2.0f * xy + x2 * y2b, MINN);
#pragma unroll
        for (int i = 0; i < 4; i++) mv[i] = (ca * mv[i] + cbf * y[i]) / den;
        proj4(mv);
        logmap04(mv);
#pragma unroll
        for (int i = 0; i < 4; i++) sT[w * 2 + s][lane + i * 32] = mv[i];
    }
    __syncthreads();
    int d = threadIdx.x >> 2;
    int q = threadIdx.x & 3;
    int s4r = (d >> 1) & 3;
    uint32_t* dst = g_logTsw + ((size_t)d * (NN / 32) + blk) * 16;
#pragma unroll
    for (int j = 0; j < 4; j++) {
        int ww = q * 4 + j;
        int P = 4 * ((ww & 3) ^ s4r) + (ww >> 2);
        dst[P] = h2pack(sT[2 * ww][d], sT[2 * ww + 1][d]);
    }
}

__global__ void k_post_agg(int nparts, int add_res, int save_res, int do_hh) {
    int w = (blockIdx.x * blockDim.x + threadIdx.x) >> 5;
    int lane = threadIdx.x & 31;
    if (w >= NN) return;
    int o = w * DD + lane;
    float v[4];
#pragma unroll
    for (int i = 0; i < 4; i++) {
        int oo = o + i * 32;
        float s = g_part[0][oo] + g_part[1][oo];
        if (nparts == 4) s += g_part[2][oo] + g_part[3][oo];
        v[i] = s;
    }
    expmap04(v); proj4(v);
    logmap04(v);
#pragma unroll
    for (int i = 0; i < 4; i++) v[i] = fmaxf(v[i], 0.0f);
    expmap04(v); proj4(v);
    if (add_res) {
#pragma unroll
        for (int i = 0; i < 4; i++) v[i] += g_res[o + i * 32];
    }
#pragma unroll
    for (int i = 0; i < 4; i++) g_h[o + i * 32] = v[i];
    if (save_res) {
#pragma unroll
        for (int i = 0; i < 4; i++) g_res[o + i * 32] = v[i];
    }
    if (do_hh) emit_hh(w, lane, v);
}

__global__ void k_cent(const float* __restrict__ cent) {
    __shared__ float sC[NCENT * 129];
    __shared__ float hs[4][DD];
    __shared__ float red[4][NCENT];
    int tx = threadIdx.x, ty = threadIdx.y;
    int tid = ty * 64 + tx;
    for (int idx = tid; idx < NCENT * DD; idx += 256)
        sC[(idx >> 7) * 129 + (idx & 127)] = cent[idx];
    int n = (blockIdx.x << 2) + ty;
    const float* hr = g_h + (size_t)n * DD;
    hs[ty][tx] = hr[tx];
    hs[ty][tx + 64] = hr[tx + 64];
    __syncthreads();
    const float* cr = sC + tx * 129;
    float x2 = 0.f, xy = 0.f, y2 = 0.f;
#pragma unroll 4
    for (int k = 0; k < DD; k++) {
        float a = hs[ty][k];
        float b = cr[k];
        x2 += a * a; xy += a * b; y2 += b * b;
    }
    float A = 1.0f - 2.0f * xy + y2;
    float Bc = 1.0f - x2;
    float nn = 0.f;
#pragma unroll 4
    for (int k = 0; k < DD; k++) {
        float t = Bc * cr[k] - A * hs[ty][k];
        nn += t * t;
    }
    float den = fmaxf(1.0f - 2.0f * xy + x2 * y2, MINN);
    float d = fmaxf(sqrtf(nn) / den, MINN);
    red[ty][tx] = 2.0f * artanhf_(d);
    __syncthreads();
    if (ty == 0)
        atomicAdd(&g_dsum[tx], red[0][tx] + red[1][tx] + red[2][tx] + red[3][tx]);
}

__global__ void k_z(const float* __restrict__ W1, const float* __restrict__ b1) {
    int w = (blockIdx.x * blockDim.x + threadIdx.x) >> 5;
    int lane = threadIdx.x & 31;
    if (w >= NN) return;
    int o = w * DD + lane;
    float v[4];
#pragma unroll
    for (int i = 0; i < 4; i++) v[i] = g_h[o + i * 32];
    logmap04(v);
#pragma unroll
    for (int cls = 0; cls < NCLS; cls++) {
        float p = 0.f;
#pragma unroll
        for (int i = 0; i < 4; i++) p += v[i] * W1[cls * DD + lane + i * 32];
        p = wsum(p);
        if (lane == 0) g_z[w * NCLS + cls] = p + b1[cls];
    }
}

__global__ void k_sm_final(float* __restrict__ out, int hr_off) {
    if (blockIdx.x < NCLS) {
        int cls = blockIdx.x;
        int t = threadIdx.x;
        __shared__ float sh[256];
        float m = -1e30f;
        for (int n = t; n < NN; n += 256) m = fmaxf(m, g_z[n * NCLS + cls]);
        sh[t] = m; __syncthreads();
        for (int s = 128; s; s >>= 1) { if (t < s) sh[t] = fmaxf(sh[t], sh[t + s]); __syncthreads(); }
        m = sh[0]; __syncthreads();
        float ss = 0.f;
        for (int n = t; n < NN; n += 256) ss += expf(g_z[n * NCLS + cls] - m);
        sh[t] = ss; __syncthreads();
        for (int s = 128; s; s >>= 1) { if (t < s) sh[t] += sh[t + s]; __syncthreads(); }
        float inv = 1.0f / sh[0];
        for (int n = t; n < NN; n += 256)
            out[7 + n * NCLS + cls] = expf(g_z[n * NCLS + cls] - m) * inv;
    } else {
        int t = threadIdx.x;
        __shared__ float sh[64];
        if (t < 64) {
            float r = g_dsum[t] * (1.0f / (float)NN);
            sh[t] = r * r;
        }
        __syncthreads();
        if (t == 0) {
            float s = 0.f;
            for (int i = 0; i < 64; i++) s += sh[i];
            sh[0] = s;
        }
        __syncthreads();
        if (t < 64) {
            float nrm = fmaxf(sqrtf(sh[0]), MINN);
            float s2 = artanhf_(nrm) / nrm;
            out[hr_off + t] = g_dsum[t] * (1.0f / (float)NN) * s2;
            if (t < NCLS) out[t] = 1.0f;
        }
    }
}

// ---------------- launch ----------------
extern "C" void kernel_launch(void* const* d_in, const int* in_sizes, int n_in,
                              void* d_out, int out_size) {
    const float* x = (const float*)d_in[0];
    const float* adj = (const float*)d_in[1];
    const float* W_conv = (const float*)d_in[3];
    const float* b_conv = (const float*)d_in[4];
    const float* cent = (const float*)d_in[5];
    const float* W1 = (const float*)d_in[8];
    const float* b1 = (const float*)d_in[9];
    float* out = (float*)d_out;

    float* p_part = 0;
    uint32_t *p_adjh = 0, *p_hh = 0, *p_logTsw = 0, *p_Wsw = 0;
    cudaGetSymbolAddress((void**)&p_part, g_part);
    cudaGetSymbolAddress((void**)&p_adjh, g_adjh);
    cudaGetSymbolAddress((void**)&p_hh, g_hh);
    cudaGetSymbolAddress((void**)&p_logTsw, g_logTsw);
    cudaGetSymbolAddress((void**)&p_Wsw, g_Wsw);

    cudaFuncSetAttribute(k_hgemm, cudaFuncAttributeMaxDynamicSharedMemorySize, SMEMSZ);

    cudaStream_t s1;
    cudaStreamCreateWithFlags(&s1, cudaStreamNonBlocking);
    cudaEvent_t eFork, ePW, eP0, eP1, eFork2, eJoin2;
    cudaEventCreateWithFlags(&eFork, cudaEventDisableTiming);
    cudaEventCreateWithFlags(&ePW, cudaEventDisableTiming);
    cudaEventCreateWithFlags(&eP0, cudaEventDisableTiming);
    cudaEventCreateWithFlags(&eP1, cudaEventDisableTiming);
    cudaEventCreateWithFlags(&eFork2, cudaEventDisableTiming);
    cudaEventCreateWithFlags(&eJoin2, cudaEventDisableTiming);

    // side stream: W/bias prep, then two adj prep chunks
    cudaEventRecord(eFork, 0);
    cudaStreamWaitEvent(s1, eFork, 0);
    k_prepWb<<<33, 256, 0, s1>>>(W_conv, b_conv);
    cudaEventRecord(ePW, s1);
    k_prep_adj<<<4096, 256, 0, s1>>>(adj, 0);
    cudaEventRecord(eP0, s1);
    k_prep_adj<<<4096, 256, 0, s1>>>(adj, 128);
    cudaEventRecord(eP1, s1);

    // main stream head
    k_in<<<NN / 8, 256>>>(x);
    cudaStreamWaitEvent(0, ePW, 0);
    k_hgemm<<<dim3(NN / BM, 2), 256, SMEMSZ>>>(
        p_hh, p_Wsw, 4, 4, 1, 0, 1.0f, p_part);
    k_post_linear_t<<<NN / 32, 512>>>(0);

    // layer-0 agg: split-K 4 in two half-launches, each grid (128,2) iters=32
    cudaStreamWaitEvent(0, eP0, 0);
    k_hgemm<<<dim3(NN / BM, 2), 256, SMEMSZ>>>(
        p_adjh, p_logTsw, 256, 256, 32, 0, ADJ_CSCALE, p_part);
    cudaStreamWaitEvent(0, eP1, 0);
    k_hgemm<<<dim3(NN / BM, 2), 256, SMEMSZ>>>(
        p_adjh, p_logTsw, 256, 256, 32, 2, ADJ_CSCALE, p_part);
    k_post_agg<<<NN / 8, 256>>>(4, 0, 0, 1);

    for (int l = 1; l < NLAYER; l++) {
        k_hgemm<<<dim3(NN / BM, 2), 256, SMEMSZ>>>(
            p_hh, p_Wsw + (size_t)l * DD * 4 * 16, 4, 4, 1, 0, 1.0f, p_part);
        k_post_linear_t<<<NN / 32, 512>>>(l);
        k_hgemm<<<dim3(NN / BM, 2), 256, SMEMSZ>>>(
            p_adjh, p_logTsw, 256, 256, 64, 0, ADJ_CSCALE, p_part);
        int ar = (l == 1 || l == 3) ? 1 : 0;
        int sr = (l == 1) ? 1 : 0;
        k_post_agg<<<NN / 8, 256>>>(2, ar, sr, (l < 3) ? 1 : 0);
    }

    // tail: k_z concurrent with k_cent
    cudaEventRecord(eFork2, 0);
    cudaStreamWaitEvent(s1, eFork2, 0);
    k_z<<<NN / 8, 256, 0, s1>>>(W1, b1);
    cudaEventRecord(eJoin2, s1);

    k_cent<<<NN / 4, dim3(64, 4)>>>(cent);
    cudaStreamWaitEvent(0, eJoin2, 0);
    k_sm_final<<<NCLS + 1, 256>>>(out, out_size - NCENT);
}

// round 17
// speedup vs baseline: 1.0643x; 1.0551x over previous
#include <cuda_runtime.h>
#include <cuda_fp16.h>
#include <math.h>
#include <stdint.h>

#define NN 8192
#define DD 128
#define NCENT 64
#define NCLS 7
#define NLAYER 4

#define MINN 1e-15f
#define EPSF 1e-5f
#define MAXNRM (1.0f - 1e-5f)

#define BM 64
#define STAGE_WORDS 6144
#define SMEMSZ (3 * STAGE_WORDS * 4)
#define FLSMEM 58368  // W 32768 + A 8192 + C 17408 bytes

#define ADJ_SCALE 8192.0f
#define ADJ_CSCALE 0.0001220703125f  // 2^-13

// ---------------- scratch ----------------
static __device__ uint32_t g_adjh[(size_t)NN * (NN / 32) * 16];
static __device__ uint32_t g_hh[NN * 4 * 16];
static __device__ float g_h[NN * DD];
static __device__ float g_res[NN * DD];
static __device__ uint32_t g_logTsw[DD * (NN / 32) * 16];
static __device__ float g_part[4][NN * DD];
static __device__ float g_hypb[NLAYER * DD];
static __device__ uint32_t g_Wsw[NLAYER * DD * 4 * 16];
static __device__ float g_dsum[NCENT];
static __device__ float g_z[NN * NCLS];

// ---------------- helpers ----------------
__device__ __forceinline__ float wsum(float v) {
    v += __shfl_xor_sync(0xffffffffu, v, 16);
    v += __shfl_xor_sync(0xffffffffu, v, 8);
    v += __shfl_xor_sync(0xffffffffu, v, 4);
    v += __shfl_xor_sync(0xffffffffu, v, 2);
    v += __shfl_xor_sync(0xffffffffu, v, 1);
    return v;
}
__device__ __forceinline__ float artanhf_(float x) {
    x = fminf(fmaxf(x, -1.0f + EPSF), 1.0f - EPSF);
    return 0.5f * (log1pf(x) - log1pf(-x));
}
__device__ __forceinline__ float rnorm4(const float v[4]) {
    float s = v[0] * v[0] + v[1] * v[1] + v[2] * v[2] + v[3] * v[3];
    s = wsum(s);
    return fmaxf(sqrtf(s), MINN);
}
__device__ __forceinline__ void logmap04(float v[4]) {
    float n = rnorm4(v);
    float s = artanhf_(n) / n;
    v[0] *= s; v[1] *= s; v[2] *= s; v[3] *= s;
}
// proj(expmap0(v)) with one norm: scale = min(tanh n, 1-eps)/n
__device__ __forceinline__ void expproj4(float v[4]) {
    float n = rnorm4(v);
    float s = fminf(tanhf(n), MAXNRM) / n;
    v[0] *= s; v[1] *= s; v[2] *= s; v[3] *= s;
}
__device__ __forceinline__ uint32_t h2pack(float a, float b) {
    __half2 h = __floats2half2_rn(a, b);
    return *(uint32_t*)&h;
}
__device__ __forceinline__ void mmah16(float c[4], uint32_t a0, uint32_t a1,
                                       uint32_t a2, uint32_t a3,
                                       uint32_t b0, uint32_t b1) {
    asm volatile(
        "mma.sync.aligned.m16n8k16.row.col.f32.f16.f16.f32 "
        "{%0,%1,%2,%3},{%4,%5,%6,%7},{%8,%9},{%0,%1,%2,%3};"
        : "+f"(c[0]), "+f"(c[1]), "+f"(c[2]), "+f"(c[3])
        : "r"(a0), "r"(a1), "r"(a2), "r"(a3), "r"(b0), "r"(b1));
}
__device__ __forceinline__ uint32_t smem_u32(const void* p) {
    uint32_t a;
    asm("{ .reg .u64 t; cvta.to.shared.u64 t, %1; cvt.u32.u64 %0, t; }" : "=r"(a) : "l"(p));
    return a;
}
__device__ __forceinline__ void cpa16(uint32_t dst, const void* src) {
    asm volatile("cp.async.cg.shared.global [%0], [%1], 16;" :: "r"(dst), "l"(src));
}
#define CPA_COMMIT() asm volatile("cp.async.commit_group;" ::: "memory")
#define CPA_WAIT1() asm volatile("cp.async.wait_group 1;" ::: "memory")
#define CPA_WAIT0() asm volatile("cp.async.wait_group 0;" ::: "memory")

// ---------------- fp16 GEMM: BM=64, BN=128, BK=64, 8 warps (agg only) ------
__global__ void __launch_bounds__(256, 2)
k_hgemm(const uint32_t* __restrict__ Asw, const uint32_t* __restrict__ Bsw,
        int kbA, int kbB, int iters, int part0, float cscale,
        float* __restrict__ Cbase) {
    extern __shared__ uint32_t smh[];
    const uint32_t smb = smem_u32(smh);
    const int tid = threadIdx.x;
    const int m0 = blockIdx.x * BM;
    const int kpart = part0 + blockIdx.y;
    const int kb0 = kpart * 2 * iters;
    float* Cout = Cbase + (size_t)kpart * NN * DD;

    int arr[2], ajj[2];
    uint32_t adst[2];
#pragma unroll
    for (int p = 0; p < 2; p++) {
        int idx = p * 256 + tid;
        int r = idx >> 3, j = idx & 7;
        arr[p] = r; ajj[p] = j;
        adst[p] = (uint32_t)((r * 32 + (((j >> 2) ^ (r & 1)) << 4) + (j & 3) * 4) * 4);
    }
    int brr[4], bjj[4];
    uint32_t bdst[4];
#pragma unroll
    for (int p = 0; p < 4; p++) {
        int idx = p * 256 + tid;
        int r = idx >> 3, j = idx & 7;
        brr[p] = r; bjj[p] = j;
        bdst[p] = (uint32_t)(8192 + (r * 32 + (((j >> 2) ^ (r & 1)) << 4) + (j & 3) * 4) * 4);
    }
    const uint32_t* aBase = Asw + (size_t)m0 * kbA * 16 + (size_t)kb0 * 16;
    const uint32_t* bBase = Bsw + (size_t)kb0 * 16;

#define ISSUE(stage, it)                                                      \
    do {                                                                      \
        uint32_t _s = smb + (uint32_t)(stage) * (STAGE_WORDS * 4);            \
        _Pragma("unroll") for (int p = 0; p < 2; p++)                         \
            cpa16(_s + adst[p],                                               \
                  aBase + (size_t)arr[p] * kbA * 16 + (it) * 32 + ajj[p] * 4);\
        _Pragma("unroll") for (int p = 0; p < 4; p++)                         \
            cpa16(_s + bdst[p],                                               \
                  bBase + (size_t)brr[p] * kbB * 16 + (it) * 32 + bjj[p] * 4);\
    } while (0)

    const int w = tid >> 5, lane = tid & 31;
    const int rr = lane >> 2, c = lane & 3;
    const int m0w = (w & 1) * 32, n0w = (w >> 1) * 32;
    const int pcw = 4 * (c ^ ((rr >> 1) & 3));
    const int rh = (rr & 1) << 4;
    int hoff[2];
    hoff[0] = (0 ^ rh) + pcw;
    hoff[1] = (16 ^ rh) + pcw;

    float acc[2][4][4];
#pragma unroll
    for (int mt = 0; mt < 2; mt++)
#pragma unroll
        for (int nt = 0; nt < 4; nt++)
#pragma unroll
            for (int e = 0; e < 4; e++) acc[mt][nt][e] = 0.0f;

    ISSUE(0, 0); CPA_COMMIT();
    if (iters > 1) ISSUE(1, 1);
    CPA_COMMIT();

    for (int i = 0; i < iters; i++) {
        if (i + 2 < iters) { CPA_WAIT1(); } else { CPA_WAIT0(); }
        __syncthreads();
        if (i + 2 < iters) ISSUE((i + 2) % 3, i + 2);
        CPA_COMMIT();

        const uint32_t* sA = smh + (size_t)(i % 3) * STAGE_WORDS;
        const uint32_t* sB = sA + 2048;
#pragma unroll
        for (int hb = 0; hb < 2; hb++) {
            uint4 a0[2], a1[2];
#pragma unroll
            for (int mt = 0; mt < 2; mt++) {
                int base = (m0w + mt * 16 + rr) * 32 + hoff[hb];
                a0[mt] = *(const uint4*)(sA + base);
                a1[mt] = *(const uint4*)(sA + base + 256);
            }
#pragma unroll
            for (int nt = 0; nt < 4; nt++) {
                uint4 b = *(const uint4*)(sB + (n0w + nt * 8 + rr) * 32 + hoff[hb]);
#pragma unroll
                for (int mt = 0; mt < 2; mt++)
                    mmah16(acc[mt][nt], a0[mt].x, a1[mt].x, a0[mt].y, a1[mt].y, b.x, b.y);
#pragma unroll
                for (int mt = 0; mt < 2; mt++)
                    mmah16(acc[mt][nt], a0[mt].z, a1[mt].z, a0[mt].w, a1[mt].w, b.z, b.w);
            }
        }
    }
#undef ISSUE

#pragma unroll
    for (int mt = 0; mt < 2; mt++) {
        int row = m0 + m0w + mt * 16 + rr;
#pragma unroll
        for (int nt = 0; nt < 4; nt++) {
            int col = n0w + nt * 8 + 2 * c;
            *(float2*)&Cout[(size_t)row * DD + col] =
                make_float2(acc[mt][nt][0] * cscale, acc[mt][nt][1] * cscale);
            *(float2*)&Cout[(size_t)(row + 8) * DD + col] =
                make_float2(acc[mt][nt][2] * cscale, acc[mt][nt][3] * cscale);
        }
    }
}

// ---------------- fused W-GEMM + post_linear + transpose ----------------
// Block = 32 nodes, 512 threads (16 warps). smem: W[kb][row][16] (8192 w),
// A[kb][row][16] (2048 w at 8192), C 32x136 fp32 (at 10240). sT aliases W.
__global__ void __launch_bounds__(512, 2)
k_fused_lin(int l) {
    extern __shared__ uint32_t sm[];
    const uint32_t smb = smem_u32(sm);
    const int tid = threadIdx.x;
    const int blk = blockIdx.x;
    const int n0 = blk * 32;

    const uint32_t* Wsrc = g_Wsw + (size_t)l * DD * 4 * 16;
#pragma unroll
    for (int p = 0; p < 4; p++) {
        int idx = p * 512 + tid;
        int r = idx >> 4, rem = idx & 15;
        int kb = rem >> 2, j = rem & 3;
        cpa16(smb + (uint32_t)((kb * 2048 + r * 16 + j * 4) * 4),
              Wsrc + (size_t)r * 64 + kb * 16 + j * 4);
    }
    {
        int r = tid >> 4, rem = tid & 15;
        int kb = rem >> 2, j = rem & 3;
        cpa16(smb + (uint32_t)((8192 + kb * 512 + r * 16 + j * 4) * 4),
              g_hh + (size_t)(n0 + r) * 64 + kb * 16 + j * 4);
    }
    CPA_COMMIT();
    CPA_WAIT0();
    __syncthreads();

    const int w = tid >> 5, lane = tid & 31;
    const int rr = lane >> 2, c = lane & 3;
    const int mw = (w & 1) * 16, nw = (w >> 1) * 16;
    const int pcw = 4 * (c ^ ((rr >> 1) & 3));

    float acc[2][4];
#pragma unroll
    for (int nt = 0; nt < 2; nt++)
#pragma unroll
        for (int e = 0; e < 4; e++) acc[nt][e] = 0.0f;

#pragma unroll
    for (int kb = 0; kb < 4; kb++) {
        const uint32_t* sA = sm + 8192 + kb * 512;
        const uint32_t* sW = sm + kb * 2048;
        uint4 a0 = *(const uint4*)(sA + (mw + rr) * 16 + pcw);
        uint4 a1 = *(const uint4*)(sA + (mw + rr + 8) * 16 + pcw);
#pragma unroll
        for (int nt = 0; nt < 2; nt++) {
            uint4 b = *(const uint4*)(sW + (nw + nt * 8 + rr) * 16 + pcw);
            mmah16(acc[nt], a0.x, a1.x, a0.y, a1.y, b.x, b.y);
            mmah16(acc[nt], a0.z, a1.z, a0.w, a1.w, b.z, b.w);
        }
    }
    float* Cs = (float*)(sm + 10240);  // 32 x 136
#pragma unroll
    for (int nt = 0; nt < 2; nt++) {
        int col = nw + nt * 8 + 2 * c;
        *(float2*)&Cs[(mw + rr) * 136 + col] = make_float2(acc[nt][0], acc[nt][1]);
        *(float2*)&Cs[(mw + rr + 8) * 136 + col] = make_float2(acc[nt][2], acc[nt][3]);
    }
    __syncthreads();

    // mobius chain: 2 nodes per warp
    float (*sT)[129] = (float(*)[129])sm;  // aliases W region (done with W)
    float y[4];
#pragma unroll
    for (int i = 0; i < 4; i++) y[i] = g_hypb[l * DD + lane + i * 32];
    float y2b = wsum(y[0] * y[0] + y[1] * y[1] + y[2] * y[2] + y[3] * y[3]);

#pragma unroll
    for (int s = 0; s < 2; s++) {
        int nl = w * 2 + s;
        int o = (n0 + nl) * DD + lane;
        float mv[4], hx[4];
#pragma unroll
        for (int i = 0; i < 4; i++) {
            mv[i] = Cs[nl * 136 + lane + i * 32];
            hx[i] = g_h[o + i * 32];
        }
        float xn = rnorm4(hx);
        float mxn = rnorm4(mv);
        // mobius_matvec scale with fused proj: min(tanh,1-eps)
        float sc = fminf(tanhf(mxn / xn * artanhf_(xn)), MAXNRM) / mxn;
#pragma unroll
        for (int i = 0; i < 4; i++) mv[i] *= sc;
        float x2 = wsum(mv[0] * mv[0] + mv[1] * mv[1] + mv[2] * mv[2] + mv[3] * mv[3]);
        float xy = wsum(mv[0] * y[0] + mv[1] * y[1] + mv[2] * y[2] + mv[3] * y[3]);
        float ca = 1.0f + 2.0f * xy + y2b;
        float cbf = 1.0f - x2;
        float den = fmaxf(1.0f + 2.0f * xy + x2 * y2b, MINN);
#pragma unroll
        for (int i = 0; i < 4; i++) mv[i] = (ca * mv[i] + cbf * y[i]) / den;
        logmap04(mv);  // proj+logmap fused (artanh clips)
#pragma unroll
        for (int i = 0; i < 4; i++) sT[nl][lane + i * 32] = mv[i];
    }
    __syncthreads();
    int d = tid >> 2;
    int q = tid & 3;
    int s4r = (d >> 1) & 3;
    uint32_t* dst = g_logTsw + ((size_t)d * (NN / 32) + blk) * 16;
#pragma unroll
    for (int j = 0; j < 4; j++) {
        int ww = q * 4 + j;
        int P = 4 * ((ww & 3) ^ s4r) + (ww >> 2);
        dst[P] = h2pack(sT[2 * ww][d], sT[2 * ww + 1][d]);
    }
}

// ---------------- prep kernels ----------------
__global__ void k_prep_adj(const float* __restrict__ adj, int kboff) {
    int unit = blockIdx.x * 256 + threadIdx.x;
    int row = unit >> 7, kb = (unit & 127) + kboff;
    const float* src = adj + (size_t)row * NN + kb * 32;
    uint32_t* dst = g_adjh + ((size_t)row * 256 + kb) * 16;
    float fl[32];
#pragma unroll
    for (int q = 0; q < 8; q++) *(float4*)(fl + q * 4) = *(const float4*)(src + q * 4);
    int s4r = (row >> 1) & 3;
#pragma unroll
    for (int c = 0; c < 4; c++) {
        uint4 o;
        o.x = h2pack(fl[2 * c] * ADJ_SCALE, fl[2 * c + 1] * ADJ_SCALE);
        o.y = h2pack(fl[2 * (c + 4)] * ADJ_SCALE, fl[2 * (c + 4) + 1] * ADJ_SCALE);
        o.z = h2pack(fl[2 * (c + 8)] * ADJ_SCALE, fl[2 * (c + 8) + 1] * ADJ_SCALE);
        o.w = h2pack(fl[2 * (c + 12)] * ADJ_SCALE, fl[2 * (c + 12) + 1] * ADJ_SCALE);
        *(uint4*)(dst + 4 * (c ^ s4r)) = o;
    }
}

__global__ void k_prepWb(const float* __restrict__ W, const float* __restrict__ b) {
    if (blockIdx.x < 32) {
        int idx = blockIdx.x * 256 + threadIdx.x;
        int unit = idx >> 2, sub = idx & 3;
        int l = unit >> 9;
        int r = (unit >> 2) & 127;
        int kb = unit & 3;
        const float* src = W + ((size_t)(l * 128 + r)) * 128 + kb * 32;
        uint32_t* dst = g_Wsw + ((size_t)((l * 128 + r) * 4 + kb)) * 16;
        int s4r = (r >> 1) & 3;
#pragma unroll
        for (int j = 0; j < 4; j++) {
            int ww = sub * 4 + j;
            int P = 4 * ((ww & 3) ^ s4r) + (ww >> 2);
            dst[P] = h2pack(src[2 * ww], src[2 * ww + 1]);
        }
    } else if (threadIdx.x < 128) {
        int l = threadIdx.x >> 5;
        int lane = threadIdx.x & 31;
        float v[4];
#pragma unroll
        for (int i = 0; i < 4; i++) v[i] = b[l * DD + lane + i * 32];
        expproj4(v);
#pragma unroll
        for (int i = 0; i < 4; i++) g_hypb[l * DD + lane + i * 32] = v[i];
    }
}

__device__ __forceinline__ void emit_hh(int row, int lane, const float v[4]) {
    float vn[4];
#pragma unroll
    for (int i = 0; i < 4; i++) vn[i] = __shfl_down_sync(0xffffffffu, v[i], 1);
    if (!(lane & 1)) {
        int s4r = (row >> 1) & 3;
        int ww = lane >> 1;
        int P = 4 * ((ww & 3) ^ s4r) + (ww >> 2);
        uint32_t* dst = g_hh + (size_t)row * 64 + P;
#pragma unroll
        for (int i = 0; i < 4; i++) dst[i * 16] = h2pack(v[i], vn[i]);
    }
}

// ---------------- pointwise ----------------
__global__ void k_in(const float* __restrict__ x) {
    if (blockIdx.x == 0 && threadIdx.x < NCENT) g_dsum[threadIdx.x] = 0.0f;
    int w = (blockIdx.x * blockDim.x + threadIdx.x) >> 5;
    int lane = threadIdx.x & 31;
    if (w >= NN) return;
    const float* r = x + w * DD + lane;
    float v[4];
#pragma unroll
    for (int i = 0; i < 4; i++) v[i] = r[i * 32];
    expproj4(v);
    int o = w * DD + lane;
#pragma unroll
    for (int i = 0; i < 4; i++) {
        g_h[o + i * 32] = v[i];
        g_res[o + i * 32] = v[i];
    }
    emit_hh(w, lane, v);
}

__global__ void k_post_agg(int nparts, int add_res, int save_res, int do_hh) {
    int w = (blockIdx.x * blockDim.x + threadIdx.x) >> 5;
    int lane = threadIdx.x & 31;
    if (w >= NN) return;
    int o = w * DD + lane;
    float v[4];
#pragma unroll
    for (int i = 0; i < 4; i++) {
        int oo = o + i * 32;
        float s = g_part[0][oo] + g_part[1][oo];
        if (nparts == 4) s += g_part[2][oo] + g_part[3][oo];
        v[i] = s;
    }
    // logmap0(proj(expmap0(v))) == v unless tanh(||v||) clamps
    {
        float n = rnorm4(v);
        float th = tanhf(n);
        if (th > MAXNRM) {
            float s = artanhf_(th) / n;
#pragma unroll
            for (int i = 0; i < 4; i++) v[i] *= s;
        }
    }
#pragma unroll
    for (int i = 0; i < 4; i++) v[i] = fmaxf(v[i], 0.0f);
    expproj4(v);
    if (add_res) {
#pragma unroll
        for (int i = 0; i < 4; i++) v[i] += g_res[o + i * 32];
    }
#pragma unroll
    for (int i = 0; i < 4; i++) g_h[o + i * 32] = v[i];
    if (save_res) {
#pragma unroll
        for (int i = 0; i < 4; i++) g_res[o + i * 32] = v[i];
    }
    if (do_hh) emit_hh(w, lane, v);
}

__global__ void k_cent(const float* __restrict__ cent) {
    __shared__ float sC[NCENT * 129];
    __shared__ float hs[4][DD];
    __shared__ float red[4][NCENT];
    int tx = threadIdx.x, ty = threadIdx.y;
    int tid = ty * 64 + tx;
    for (int idx = tid; idx < NCENT * DD; idx += 256)
        sC[(idx >> 7) * 129 + (idx & 127)] = cent[idx];
    int n = (blockIdx.x << 2) + ty;
    const float* hr = g_h + (size_t)n * DD;
    hs[ty][tx] = hr[tx];
    hs[ty][tx + 64] = hr[tx + 64];
    __syncthreads();
    const float* cr = sC + tx * 129;
    float x2 = 0.f, xy = 0.f, y2 = 0.f;
#pragma unroll 4
    for (int k = 0; k < DD; k++) {
        float a = hs[ty][k];
        float b = cr[k];
        x2 += a * a; xy += a * b; y2 += b * b;
    }
    float A = 1.0f - 2.0f * xy + y2;
    float Bc = 1.0f - x2;
    float nn = 0.f;
#pragma unroll 4
    for (int k = 0; k < DD; k++) {
        float t = Bc * cr[k] - A * hs[ty][k];
        nn += t * t;
    }
    float den = fmaxf(1.0f - 2.0f * xy + x2 * y2, MINN);
    float d = fmaxf(sqrtf(nn) / den, MINN);
    red[ty][tx] = 2.0f * artanhf_(d);
    __syncthreads();
    if (ty == 0)
        atomicAdd(&g_dsum[tx], red[0][tx] + red[1][tx] + red[2][tx] + red[3][tx]);
}

__global__ void k_z(const float* __restrict__ W1, const float* __restrict__ b1) {
    int w = (blockIdx.x * blockDim.x + threadIdx.x) >> 5;
    int lane = threadIdx.x & 31;
    if (w >= NN) return;
    int o = w * DD + lane;
    float v[4];
#pragma unroll
    for (int i = 0; i < 4; i++) v[i] = g_h[o + i * 32];
    logmap04(v);
#pragma unroll
    for (int cls = 0; cls < NCLS; cls++) {
        float p = 0.f;
#pragma unroll
        for (int i = 0; i < 4; i++) p += v[i] * W1[cls * DD + lane + i * 32];
        p = wsum(p);
        if (lane == 0) g_z[w * NCLS + cls] = p + b1[cls];
    }
}

__global__ void k_sm_final(float* __restrict__ out, int hr_off) {
    if (blockIdx.x < NCLS) {
        int cls = blockIdx.x;
        int t = threadIdx.x;
        __shared__ float sh[256];
        float m = -1e30f;
        for (int n = t; n < NN; n += 256) m = fmaxf(m, g_z[n * NCLS + cls]);
        sh[t] = m; __syncthreads();
        for (int s = 128; s; s >>= 1) { if (t < s) sh[t] = fmaxf(sh[t], sh[t + s]); __syncthreads(); }
        m = sh[0]; __syncthreads();
        float ss = 0.f;
        for (int n = t; n < NN; n += 256) ss += expf(g_z[n * NCLS + cls] - m);
        sh[t] = ss; __syncthreads();
        for (int s = 128; s; s >>= 1) { if (t < s) sh[t] += sh[t + s]; __syncthreads(); }
        float inv = 1.0f / sh[0];
        for (int n = t; n < NN; n += 256)
            out[7 + n * NCLS + cls] = expf(g_z[n * NCLS + cls] - m) * inv;
    } else {
        int t = threadIdx.x;
        __shared__ float sh[64];
        if (t < 64) {
            float r = g_dsum[t] * (1.0f / (float)NN);
            sh[t] = r * r;
        }
        __syncthreads();
        if (t == 0) {
            float s = 0.f;
            for (int i = 0; i < 64; i++) s += sh[i];
            sh[0] = s;
        }
        __syncthreads();
        if (t < 64) {
            float nrm = fmaxf(sqrtf(sh[0]), MINN);
            float s2 = artanhf_(nrm) / nrm;
            out[hr_off + t] = g_dsum[t] * (1.0f / (float)NN) * s2;
            if (t < NCLS) out[t] = 1.0f;
        }
    }
}

// ---------------- launch ----------------
extern "C" void kernel_launch(void* const* d_in, const int* in_sizes, int n_in,
                              void* d_out, int out_size) {
    const float* x = (const float*)d_in[0];
    const float* adj = (const float*)d_in[1];
    const float* W_conv = (const float*)d_in[3];
    const float* b_conv = (const float*)d_in[4];
    const float* cent = (const float*)d_in[5];
    const float* W1 = (const float*)d_in[8];
    const float* b1 = (const float*)d_in[9];
    float* out = (float*)d_out;

    float* p_part = 0;
    uint32_t *p_adjh = 0, *p_logTsw = 0;
    cudaGetSymbolAddress((void**)&p_part, g_part);
    cudaGetSymbolAddress((void**)&p_adjh, g_adjh);
    cudaGetSymbolAddress((void**)&p_logTsw, g_logTsw);

    cudaFuncSetAttribute(k_hgemm, cudaFuncAttributeMaxDynamicSharedMemorySize, SMEMSZ);
    cudaFuncSetAttribute(k_fused_lin, cudaFuncAttributeMaxDynamicSharedMemorySize, FLSMEM);

    cudaStream_t s1;
    cudaStreamCreateWithFlags(&s1, cudaStreamNonBlocking);
    cudaEvent_t eFork, ePW, eP0, eP1, eFork2, eJoin2;
    cudaEventCreateWithFlags(&eFork, cudaEventDisableTiming);
    cudaEventCreateWithFlags(&ePW, cudaEventDisableTiming);
    cudaEventCreateWithFlags(&eP0, cudaEventDisableTiming);
    cudaEventCreateWithFlags(&eP1, cudaEventDisableTiming);
    cudaEventCreateWithFlags(&eFork2, cudaEventDisableTiming);
    cudaEventCreateWithFlags(&eJoin2, cudaEventDisableTiming);

    // side stream: W/bias prep, then two adj prep chunks
    cudaEventRecord(eFork, 0);
    cudaStreamWaitEvent(s1, eFork, 0);
    k_prepWb<<<33, 256, 0, s1>>>(W_conv, b_conv);
    cudaEventRecord(ePW, s1);
    k_prep_adj<<<4096, 256, 0, s1>>>(adj, 0);
    cudaEventRecord(eP0, s1);
    k_prep_adj<<<4096, 256, 0, s1>>>(adj, 128);
    cudaEventRecord(eP1, s1);

    // main stream head
    k_in<<<NN / 8, 256>>>(x);
    cudaStreamWaitEvent(0, ePW, 0);
    k_fused_lin<<<NN / 32, 512, FLSMEM>>>(0);

    // layer-0 agg: split-K 4 in two half-launches, each grid (128,2) iters=32
    cudaStreamWaitEvent(0, eP0, 0);
    k_hgemm<<<dim3(NN / BM, 2), 256, SMEMSZ>>>(
        p_adjh, p_logTsw, 256, 256, 32, 0, ADJ_CSCALE, p_part);
    cudaStreamWaitEvent(0, eP1, 0);
    k_hgemm<<<dim3(NN / BM, 2), 256, SMEMSZ>>>(
        p_adjh, p_logTsw, 256, 256, 32, 2, ADJ_CSCALE, p_part);
    k_post_agg<<<NN / 8, 256>>>(4, 0, 0, 1);

    for (int l = 1; l < NLAYER; l++) {
        k_fused_lin<<<NN / 32, 512, FLSMEM>>>(l);
        k_hgemm<<<dim3(NN / BM, 2), 256, SMEMSZ>>>(
            p_adjh, p_logTsw, 256, 256, 64, 0, ADJ_CSCALE, p_part);
        int ar = (l == 1 || l == 3) ? 1 : 0;
        int sr = (l == 1) ? 1 : 0;
        k_post_agg<<<NN / 8, 256>>>(2, ar, sr, (l < 3) ? 1 : 0);
    }

    // tail: k_z concurrent with k_cent
    cudaEventRecord(eFork2, 0);
    cudaStreamWaitEvent(s1, eFork2, 0);
    k_z<<<NN / 8, 256, 0, s1>>>(W1, b1);
    cudaEventRecord(eJoin2, s1);

    k_cent<<<NN / 4, dim3(64, 4)>>>(cent);
    cudaStreamWaitEvent(0, eJoin2, 0);
    k_sm_final<<<NCLS + 1, 256>>>(out, out_size - NCENT);
}